// round 1
// baseline (speedup 1.0000x reference)
#include <cuda_runtime.h>

#define S_TOK 8192
#define MDIM  1024
#define EDIM  8
#define HDIM  4096
#define CAP   1024

// ---------------- scratch (device globals; no allocation in kernel_launch) ----
__device__ float g_gate[S_TOK];           // gate value (0 if dropped)
__device__ int   g_exp[S_TOK];
__device__ int   g_loc[S_TOK];
__device__ float g_sumgate[EDIM];
__device__ int   g_count[EDIM];
__device__ float g_laux;
__device__ float g_disp[(size_t)EDIM * CAP * MDIM];   // 32 MB
__device__ float g_h[(size_t)S_TOK * HDIM];           // 128 MB
__device__ float g_eout[(size_t)S_TOK * MDIM];        // 32 MB

// ---------------- init accumulators ----------------
__global__ void init_kernel() {
    int t = threadIdx.x;
    if (t < EDIM) { g_sumgate[t] = 0.f; g_count[t] = 0; }
}

// ---------------- gating: logits -> softmax -> argmax -------------
// 1 warp per token, 8 warps/block, grid = S/8
__global__ __launch_bounds__(256) void gate_kernel(const float* __restrict__ x,
                                                   const float* __restrict__ wg) {
    __shared__ float swg[MDIM * EDIM];   // 32 KB
    __shared__ float ssum[EDIM];
    __shared__ int   scnt[EDIM];
    int tid = threadIdx.x;
    for (int i = tid; i < MDIM * EDIM; i += 256) swg[i] = wg[i];
    if (tid < EDIM) { ssum[tid] = 0.f; scnt[tid] = 0; }
    __syncthreads();

    int warp = tid >> 5, lane = tid & 31;
    int t = blockIdx.x * 8 + warp;
    const float* xr = x + (size_t)t * MDIM;

    float acc[EDIM];
#pragma unroll
    for (int e = 0; e < EDIM; e++) acc[e] = 0.f;
    for (int m = lane; m < MDIM; m += 32) {
        float xv = xr[m];
#pragma unroll
        for (int e = 0; e < EDIM; e++) acc[e] = fmaf(xv, swg[m * EDIM + e], acc[e]);
    }
#pragma unroll
    for (int e = 0; e < EDIM; e++)
#pragma unroll
        for (int o = 16; o > 0; o >>= 1)
            acc[e] += __shfl_xor_sync(0xffffffffu, acc[e], o);

    if (lane == 0) {
        float mx = acc[0]; int bi = 0;
#pragma unroll
        for (int e = 1; e < EDIM; e++) if (acc[e] > mx) { mx = acc[e]; bi = e; }
        float g[EDIM], sum = 0.f;
#pragma unroll
        for (int e = 0; e < EDIM; e++) { g[e] = expf(acc[e] - mx); sum += g[e]; }
        float inv = 1.f / sum;
#pragma unroll
        for (int e = 0; e < EDIM; e++) { g[e] *= inv; atomicAdd(&ssum[e], g[e]); }
        atomicAdd(&scnt[bi], 1);
        g_exp[t]  = bi;
        g_gate[t] = g[bi];
    }
    __syncthreads();
    if (tid < EDIM) {
        atomicAdd(&g_sumgate[tid], ssum[tid]);
        atomicAdd(&g_count[tid], scnt[tid]);
    }
}

// ---------------- per-expert cumsum (token order), capacity drop, l_aux ------
// single block of 256 threads; thread i owns tokens [i*32, i*32+32)
__global__ __launch_bounds__(256) void scan_kernel() {
    __shared__ int sc[256][EDIM];
    int tid = threadIdx.x;
    int t0 = tid * 32;
    int cnt[EDIM];
#pragma unroll
    for (int e = 0; e < EDIM; e++) cnt[e] = 0;
    for (int j = 0; j < 32; j++) cnt[g_exp[t0 + j]]++;
#pragma unroll
    for (int e = 0; e < EDIM; e++) sc[tid][e] = cnt[e];
    __syncthreads();
    if (tid < EDIM) {
        int run = 0;
        for (int i = 0; i < 256; i++) { int c = sc[i][tid]; sc[i][tid] = run; run += c; }
    }
    __syncthreads();
    int base[EDIM];
#pragma unroll
    for (int e = 0; e < EDIM; e++) base[e] = sc[tid][e];
    for (int j = 0; j < 32; j++) {
        int t = t0 + j;
        int e = g_exp[t];
        int loc = base[e]++;
        g_loc[t] = loc;
        if (loc >= CAP) g_gate[t] = 0.f;  // dropped
    }
    if (tid == 0) {
        float l = 0.f;
        for (int e = 0; e < EDIM; e++)
            l += (g_sumgate[e] / (float)S_TOK) * ((float)g_count[e] / (float)S_TOK);
        g_laux = l * (float)EDIM;
    }
}

// ---------------- dispatch: gather kept tokens into [e, c, m] ----------------
// 1 block per token, 256 threads, float4 copy. Unfilled slots are never read.
__global__ __launch_bounds__(256) void scatter_kernel(const float* __restrict__ x) {
    int t = blockIdx.x;
    float g = g_gate[t];
    if (g <= 0.f) return;
    int e = g_exp[t], loc = g_loc[t];
    const float4* src = (const float4*)(x + (size_t)t * MDIM);
    float4* dst = (float4*)(g_disp + ((size_t)e * CAP + loc) * MDIM);
    dst[threadIdx.x] = src[threadIdx.x];
}

// ---------------- expert GEMM: C[8192,N] = A[8192,K] @ B[expert][K,N] --------
// classic 128x128x8 SGEMM, 256 threads, 8x8 per-thread micro-tile
template <int K, int N, bool RELU>
__global__ __launch_bounds__(256, 2) void sgemm_kernel(const float* __restrict__ A,
                                                       const float* __restrict__ B,
                                                       float* __restrict__ C) {
    __shared__ float As[8][128];
    __shared__ float Bs[8][128];
    int tid = threadIdx.x;
    int row0 = blockIdx.y * 128;
    int col0 = blockIdx.x * 128;
    const float* Be = B + (size_t)(blockIdx.y >> 3) * K * N;  // expert = row0/1024

    int arow = tid >> 1, acol = (tid & 1) * 4;
    int brow = tid >> 5, bcol = (tid & 31) * 4;
    const float* Ap = A + (size_t)(row0 + arow) * K + acol;
    const float* Bp = Be + (size_t)brow * N + col0 + bcol;

    int tx = tid & 15, ty = tid >> 4;
    float cacc[8][8];
#pragma unroll
    for (int i = 0; i < 8; i++)
#pragma unroll
        for (int j = 0; j < 8; j++) cacc[i][j] = 0.f;

    for (int k0 = 0; k0 < K; k0 += 8) {
        float4 av = *(const float4*)(Ap + k0);
        float4 bv = *(const float4*)(Bp + (size_t)k0 * N);
        As[acol + 0][arow] = av.x;
        As[acol + 1][arow] = av.y;
        As[acol + 2][arow] = av.z;
        As[acol + 3][arow] = av.w;
        *(float4*)&Bs[brow][bcol] = bv;
        __syncthreads();
#pragma unroll
        for (int k = 0; k < 8; k++) {
            float a[8], b[8];
            *(float4*)(a)     = *(const float4*)&As[k][ty * 8];
            *(float4*)(a + 4) = *(const float4*)&As[k][ty * 8 + 4];
            *(float4*)(b)     = *(const float4*)&Bs[k][tx * 8];
            *(float4*)(b + 4) = *(const float4*)&Bs[k][tx * 8 + 4];
#pragma unroll
            for (int i = 0; i < 8; i++)
#pragma unroll
                for (int j = 0; j < 8; j++)
                    cacc[i][j] = fmaf(a[i], b[j], cacc[i][j]);
        }
        __syncthreads();
    }
#pragma unroll
    for (int i = 0; i < 8; i++) {
        float* crow = C + (size_t)(row0 + ty * 8 + i) * N + col0 + tx * 8;
#pragma unroll
        for (int j4 = 0; j4 < 2; j4++) {
            float4 v;
            v.x = cacc[i][j4 * 4 + 0];
            v.y = cacc[i][j4 * 4 + 1];
            v.z = cacc[i][j4 * 4 + 2];
            v.w = cacc[i][j4 * 4 + 3];
            if (RELU) {
                v.x = fmaxf(v.x, 0.f); v.y = fmaxf(v.y, 0.f);
                v.z = fmaxf(v.z, 0.f); v.w = fmaxf(v.w, 0.f);
            }
            *(float4*)(crow + j4 * 4) = v;
        }
    }
}

// ---------------- combine: out[t] = gate * eout[e,loc]; dropped -> 0 ---------
__global__ __launch_bounds__(256) void combine_kernel(float* __restrict__ out, int out_size) {
    int t = blockIdx.x;
    float g = g_gate[t];
    float4* dst = (float4*)(out + (size_t)t * MDIM);
    if (g > 0.f) {
        int e = g_exp[t], loc = g_loc[t];
        const float4* src = (const float4*)(g_eout + ((size_t)e * CAP + loc) * MDIM);
        float4 v = src[threadIdx.x];
        v.x *= g; v.y *= g; v.z *= g; v.w *= g;
        dst[threadIdx.x] = v;
    } else {
        dst[threadIdx.x] = make_float4(0.f, 0.f, 0.f, 0.f);
    }
    if (blockIdx.x == 0 && threadIdx.x == 0 && out_size > S_TOK * MDIM)
        out[(size_t)S_TOK * MDIM] = g_laux;  // l_aux appended after out
}

// ---------------- launch ----------------
extern "C" void kernel_launch(void* const* d_in, const int* in_sizes, int n_in,
                              void* d_out, int out_size) {
    const float* x  = (const float*)d_in[0];   // [4,2048,1024]
    const float* wg = (const float*)d_in[1];   // [1024,8]
    const float* w1 = (const float*)d_in[2];   // [8,1024,4096]
    const float* w2 = (const float*)d_in[3];   // [8,4096,1024]
    float* out = (float*)d_out;

    float *p_disp, *p_h, *p_eout;
    cudaGetSymbolAddress((void**)&p_disp, g_disp);
    cudaGetSymbolAddress((void**)&p_h,    g_h);
    cudaGetSymbolAddress((void**)&p_eout, g_eout);

    init_kernel<<<1, 32>>>();
    gate_kernel<<<S_TOK / 8, 256>>>(x, wg);
    scan_kernel<<<1, 256>>>();
    scatter_kernel<<<S_TOK, 256>>>(x);
    // FFN layer 1: [8192,1024] @ per-expert [1024,4096] -> relu -> g_h
    sgemm_kernel<MDIM, HDIM, true><<<dim3(HDIM / 128, S_TOK / 128), 256>>>(p_disp, w1, p_h);
    // FFN layer 2: [8192,4096] @ per-expert [4096,1024] -> g_eout
    sgemm_kernel<HDIM, MDIM, false><<<dim3(MDIM / 128, S_TOK / 128), 256>>>(p_h, w2, p_eout);
    combine_kernel<<<S_TOK, 256>>>(out, out_size);
}

// round 3
// speedup vs baseline: 2.9707x; 2.9707x over previous
#include <cuda_runtime.h>
#include <cstdint>

#define S_TOK 8192
#define MDIM  1024
#define EDIM  8
#define HDIM  4096
#define CAP   1024

// ======================= helpers ===========================================
__device__ __forceinline__ uint32_t smem_u32(const void* p) {
    uint32_t a;
    asm("{ .reg .u64 t; cvta.to.shared.u64 t, %1; cvt.u32.u64 %0, t; }" : "=r"(a) : "l"(p));
    return a;
}
__device__ __forceinline__ float to_tf32(float x) {
    uint32_t u;
    asm("cvt.rna.tf32.f32 %0, %1;" : "=r"(u) : "f"(x));
    return __uint_as_float(u);
}
__device__ __forceinline__ void cp_async16(uint32_t dst, const void* src) {
    asm volatile("cp.async.cg.shared.global [%0], [%1], 16;" :: "r"(dst), "l"(src));
}
#define CP_COMMIT() asm volatile("cp.async.commit_group;" ::: "memory")
#define CP_WAIT(n)  asm volatile("cp.async.wait_group %0;" :: "n"(n) : "memory")

__device__ __forceinline__ void ldmatrix_x4(uint32_t* r, uint32_t addr) {
    asm volatile("ldmatrix.sync.aligned.m8n8.x4.shared.b16 {%0,%1,%2,%3}, [%4];"
                 : "=r"(r[0]), "=r"(r[1]), "=r"(r[2]), "=r"(r[3]) : "r"(addr));
}
__device__ __forceinline__ float lds_f32(uint32_t a) {
    float v;
    asm volatile("ld.shared.f32 %0, [%1];" : "=f"(v) : "r"(a));
    return v;
}
__device__ __forceinline__ void mma_tf32(float* c, const uint32_t* a, uint32_t b0, uint32_t b1) {
    asm volatile("mma.sync.aligned.m16n8k8.row.col.f32.tf32.tf32.f32 "
                 "{%0,%1,%2,%3}, {%4,%5,%6,%7}, {%8,%9}, {%0,%1,%2,%3};"
                 : "+f"(c[0]), "+f"(c[1]), "+f"(c[2]), "+f"(c[3])
                 : "r"(a[0]), "r"(a[1]), "r"(a[2]), "r"(a[3]), "r"(b0), "r"(b1));
}

// ======================= scratch ===========================================
__device__ float g_gate[S_TOK];
__device__ int   g_exp[S_TOK];
__device__ int   g_loc[S_TOK];
__device__ float g_sumgate[EDIM];
__device__ int   g_count[EDIM];
__device__ float g_laux;
__device__ float g_disp[(size_t)EDIM * CAP * MDIM];   // tf32-rounded dispatch
__device__ float g_h[(size_t)S_TOK * HDIM];           // tf32-rounded hidden
__device__ float g_eout[(size_t)S_TOK * MDIM];

// ======================= init / gating / scan / scatter =====================
__global__ void init_kernel() {
    int t = threadIdx.x;
    if (t < EDIM) { g_sumgate[t] = 0.f; g_count[t] = 0; }
}

__global__ __launch_bounds__(256) void gate_kernel(const float* __restrict__ x,
                                                   const float* __restrict__ wg) {
    __shared__ float swg[MDIM * EDIM];
    __shared__ float ssum[EDIM];
    __shared__ int   scnt[EDIM];
    int tid = threadIdx.x;
    for (int i = tid; i < MDIM * EDIM; i += 256) swg[i] = wg[i];
    if (tid < EDIM) { ssum[tid] = 0.f; scnt[tid] = 0; }
    __syncthreads();

    int warp = tid >> 5, lane = tid & 31;
    int t = blockIdx.x * 8 + warp;
    const float* xr = x + (size_t)t * MDIM;

    float acc[EDIM];
#pragma unroll
    for (int e = 0; e < EDIM; e++) acc[e] = 0.f;
    for (int m = lane; m < MDIM; m += 32) {
        float xv = xr[m];
#pragma unroll
        for (int e = 0; e < EDIM; e++) acc[e] = fmaf(xv, swg[m * EDIM + e], acc[e]);
    }
#pragma unroll
    for (int e = 0; e < EDIM; e++)
#pragma unroll
        for (int o = 16; o > 0; o >>= 1)
            acc[e] += __shfl_xor_sync(0xffffffffu, acc[e], o);

    if (lane == 0) {
        float mx = acc[0]; int bi = 0;
#pragma unroll
        for (int e = 1; e < EDIM; e++) if (acc[e] > mx) { mx = acc[e]; bi = e; }
        float g[EDIM], sum = 0.f;
#pragma unroll
        for (int e = 0; e < EDIM; e++) { g[e] = expf(acc[e] - mx); sum += g[e]; }
        float inv = 1.f / sum;
#pragma unroll
        for (int e = 0; e < EDIM; e++) { g[e] *= inv; atomicAdd(&ssum[e], g[e]); }
        atomicAdd(&scnt[bi], 1);
        g_exp[t]  = bi;
        g_gate[t] = g[bi];
    }
    __syncthreads();
    if (tid < EDIM) {
        atomicAdd(&g_sumgate[tid], ssum[tid]);
        atomicAdd(&g_count[tid], scnt[tid]);
    }
}

__global__ __launch_bounds__(256) void scan_kernel() {
    __shared__ int sc[256][EDIM];
    int tid = threadIdx.x;
    int t0 = tid * 32;
    int cnt[EDIM];
#pragma unroll
    for (int e = 0; e < EDIM; e++) cnt[e] = 0;
    for (int j = 0; j < 32; j++) cnt[g_exp[t0 + j]]++;
#pragma unroll
    for (int e = 0; e < EDIM; e++) sc[tid][e] = cnt[e];
    __syncthreads();
    if (tid < EDIM) {
        int run = 0;
        for (int i = 0; i < 256; i++) { int c = sc[i][tid]; sc[i][tid] = run; run += c; }
    }
    __syncthreads();
    int base[EDIM];
#pragma unroll
    for (int e = 0; e < EDIM; e++) base[e] = sc[tid][e];
    for (int j = 0; j < 32; j++) {
        int t = t0 + j;
        int e = g_exp[t];
        int loc = base[e]++;
        g_loc[t] = loc;
        if (loc >= CAP) g_gate[t] = 0.f;
    }
    if (tid == 0) {
        float l = 0.f;
        for (int e = 0; e < EDIM; e++)
            l += (g_sumgate[e] / (float)S_TOK) * ((float)g_count[e] / (float)S_TOK);
        g_laux = l * (float)EDIM;
    }
}

__global__ __launch_bounds__(256) void scatter_kernel(const float* __restrict__ x) {
    int t = blockIdx.x;
    float g = g_gate[t];
    if (g <= 0.f) return;
    int e = g_exp[t], loc = g_loc[t];
    const float4* src = (const float4*)(x + (size_t)t * MDIM);
    float4* dst = (float4*)(g_disp + ((size_t)e * CAP + loc) * MDIM);
    float4 v = src[threadIdx.x];
    v.x = to_tf32(v.x); v.y = to_tf32(v.y); v.z = to_tf32(v.z); v.w = to_tf32(v.w);
    dst[threadIdx.x] = v;
}

// ======================= tf32 mma.sync GEMM ================================
// C[8192, N] = A[8192, K] @ Wexp[K, N]  (expert = blockIdx.y >> 3)
// BM=BN=128, BK=32, 256 thr (8 warps, 2x4), warp tile 64x32, 2-stage cp.async
// A smem: [128 rows][8 chunks of 16B], chunk swizzled c^(r&7)   (16 KB/stage)
// B smem: [32 k][128 n], element swizzled n^((k&3)<<3)          (16 KB/stage)
static constexpr int GSMEM_BYTES = 65536 + 1024;

template <int K, int N, bool RELU_TF32>
__global__ __launch_bounds__(256, 2) void mma_gemm(const float* __restrict__ A,
                                                   const float* __restrict__ B,
                                                   float* __restrict__ C) {
    extern __shared__ char dynsmem[];
    char* sptr = (char*)((((uintptr_t)dynsmem) + 1023) & ~(uintptr_t)1023);
    uint32_t sbase = smem_u32(sptr);

    int tid = threadIdx.x;
    int wid = tid >> 5, lane = tid & 31;
    int row0 = blockIdx.y * 128, col0 = blockIdx.x * 128;
    const float* __restrict__ Be = B + (size_t)(blockIdx.y >> 3) * (size_t)K * N;

    // ---- tile loader ----
    int lr  = tid >> 1;               // A row 0..127
    int lcb = (tid & 1) * 4;          // A chunk base (0 or 4)
    int lkr = tid >> 3;               // B k row 0..31
    int lnb = (tid & 7) * 4;          // B chunk base (0..28)

    auto load_tile = [&](int kt, int buf) {
        int k0 = kt * 32;
        uint32_t sA = sbase + (uint32_t)buf * 32768u;
        uint32_t sB = sA + 16384u;
        const float* Ag = A + (size_t)(row0 + lr) * K + k0 + lcb * 4;
        uint32_t arow = sA + (uint32_t)lr * 128u;
#pragma unroll
        for (int i = 0; i < 4; i++) {
            uint32_t c = (uint32_t)(lcb + i);
            cp_async16(arow + (((c ^ ((uint32_t)lr & 7u)) << 4)), Ag + i * 4);
        }
        const float* Bg = Be + (size_t)(k0 + lkr) * N + col0 + lnb * 4;
        uint32_t brow = sB + (uint32_t)lkr * 512u;
        uint32_t ksw = ((uint32_t)lkr & 3u) << 3;
#pragma unroll
        for (int i = 0; i < 4; i++) {
            uint32_t n0 = (uint32_t)(lnb + i) * 4u;
            cp_async16(brow + ((n0 ^ ksw) << 2), Bg + i * 4);
        }
        CP_COMMIT();
    };

    int wm = (wid & 1) * 64;          // warp M offset (0 or 64)
    int wn = (wid >> 1) * 32;         // warp N offset (0,32,64,96)

    float acc[4][4][4];
#pragma unroll
    for (int i = 0; i < 4; i++)
#pragma unroll
        for (int j = 0; j < 4; j++)
#pragma unroll
            for (int q = 0; q < 4; q++) acc[i][j][q] = 0.f;

    load_tile(0, 0);

    constexpr int KT = K / 32;
#pragma unroll 1
    for (int kt = 0; kt < KT; kt++) {
        int buf = kt & 1;
        if (kt + 1 < KT) { load_tile(kt + 1, buf ^ 1); CP_WAIT(1); }
        else             { CP_WAIT(0); }
        __syncthreads();

        uint32_t sA = sbase + (uint32_t)buf * 32768u;
        uint32_t sB = sA + 16384u;
        int l4 = lane & 3;
        uint32_t bksw = ((uint32_t)l4) << 3;
#pragma unroll
        for (int s = 0; s < 4; s++) {
            uint32_t af[4][4];
#pragma unroll
            for (int mi = 0; mi < 4; mi++) {
                int rowl = wm + mi * 16 + (lane & 15);
                uint32_t chunk = (uint32_t)(2 * s + (lane >> 4)) ^ ((uint32_t)rowl & 7u);
                ldmatrix_x4(af[mi], sA + (uint32_t)rowl * 128u + chunk * 16u);
            }
            uint32_t bw[4][2];
            int kk = s * 8 + l4;
            uint32_t bbase = sB + (uint32_t)kk * 512u;
#pragma unroll
            for (int jt = 0; jt < 4; jt++) {
                uint32_t n = (uint32_t)(wn + jt * 8 + (lane >> 2));
                uint32_t a0 = bbase + ((n ^ bksw) << 2);
                bw[jt][0] = __float_as_uint(to_tf32(lds_f32(a0)));
                bw[jt][1] = __float_as_uint(to_tf32(lds_f32(a0 + 2048u)));
            }
#pragma unroll
            for (int mi = 0; mi < 4; mi++)
#pragma unroll
                for (int jt = 0; jt < 4; jt++)
                    mma_tf32(acc[mi][jt], af[mi], bw[jt][0], bw[jt][1]);
        }
        __syncthreads();
    }

    // ---- epilogue ----
#pragma unroll
    for (int mi = 0; mi < 4; mi++) {
        int r = row0 + wm + mi * 16 + (lane >> 2);
#pragma unroll
        for (int jt = 0; jt < 4; jt++) {
            int c = col0 + wn + jt * 8 + (lane & 3) * 2;
            float v0 = acc[mi][jt][0], v1 = acc[mi][jt][1];
            float v2 = acc[mi][jt][2], v3 = acc[mi][jt][3];
            if (RELU_TF32) {
                v0 = to_tf32(fmaxf(v0, 0.f)); v1 = to_tf32(fmaxf(v1, 0.f));
                v2 = to_tf32(fmaxf(v2, 0.f)); v3 = to_tf32(fmaxf(v3, 0.f));
            }
            *(float2*)(C + (size_t)r * N + c)       = make_float2(v0, v1);
            *(float2*)(C + (size_t)(r + 8) * N + c) = make_float2(v2, v3);
        }
    }
}

// ======================= combine ===========================================
__global__ __launch_bounds__(256) void combine_kernel(float* __restrict__ out, int out_size) {
    int t = blockIdx.x;
    float g = g_gate[t];
    float4* dst = (float4*)(out + (size_t)t * MDIM);
    if (g > 0.f) {
        int e = g_exp[t], loc = g_loc[t];
        const float4* src = (const float4*)(g_eout + ((size_t)e * CAP + loc) * MDIM);
        float4 v = src[threadIdx.x];
        v.x *= g; v.y *= g; v.z *= g; v.w *= g;
        dst[threadIdx.x] = v;
    } else {
        dst[threadIdx.x] = make_float4(0.f, 0.f, 0.f, 0.f);
    }
    if (blockIdx.x == 0 && threadIdx.x == 0 && out_size > S_TOK * MDIM)
        out[(size_t)S_TOK * MDIM] = g_laux;
}

// ======================= launch ============================================
extern "C" void kernel_launch(void* const* d_in, const int* in_sizes, int n_in,
                              void* d_out, int out_size) {
    const float* x  = (const float*)d_in[0];   // [4,2048,1024]
    const float* wg = (const float*)d_in[1];   // [1024,8]
    const float* w1 = (const float*)d_in[2];   // [8,1024,4096]
    const float* w2 = (const float*)d_in[3];   // [8,4096,1024]
    float* out = (float*)d_out;

    float *p_disp, *p_h, *p_eout;
    cudaGetSymbolAddress((void**)&p_disp, g_disp);
    cudaGetSymbolAddress((void**)&p_h,    g_h);
    cudaGetSymbolAddress((void**)&p_eout, g_eout);

    static bool attr_done = false;
    if (!attr_done) {
        cudaFuncSetAttribute(mma_gemm<MDIM, HDIM, true>,
                             cudaFuncAttributeMaxDynamicSharedMemorySize, GSMEM_BYTES);
        cudaFuncSetAttribute(mma_gemm<HDIM, MDIM, false>,
                             cudaFuncAttributeMaxDynamicSharedMemorySize, GSMEM_BYTES);
        attr_done = true;
    }

    init_kernel<<<1, 32>>>();
    gate_kernel<<<S_TOK / 8, 256>>>(x, wg);
    scan_kernel<<<1, 256>>>();
    scatter_kernel<<<S_TOK, 256>>>(x);
    mma_gemm<MDIM, HDIM, true><<<dim3(HDIM / 128, S_TOK / 128), 256, GSMEM_BYTES>>>(p_disp, w1, p_h);
    mma_gemm<HDIM, MDIM, false><<<dim3(MDIM / 128, S_TOK / 128), 256, GSMEM_BYTES>>>(p_h, w2, p_eout);
    combine_kernel<<<S_TOK, 256>>>(out, out_size);
}